// round 7
// baseline (speedup 1.0000x reference)
#include <cuda_runtime.h>
#include <cuda_fp16.h>
#include <cstdint>

#define USER_NUM 100000
#define ITEM_NUM 100000
#define N_NODES  (USER_NUM + ITEM_NUM)   // 200000
#define EMB      64
#define ROWU4    8                       // 8 uint4 (16B) per row = 128B
#define NNZ      4000000
#define SCAN_CHUNK 1024
#define NUM_CHUNKS ((N_NODES + SCAN_CHUNK - 1) / SCAN_CHUNK)   // 196
#define DEG_BINS 64

// ---------------- scratch (allocation-free: __device__ globals) ----------------
__device__ int    g_rowptr[N_NODES + 1];
__device__ int    g_cursor[N_NODES];          // histogram counts, then scatter cursors
__device__ int    g_bsum[NUM_CHUNKS];
__device__ int    g_bsum2[NUM_CHUNKS];
__device__ int    g_dbin[DEG_BINS];           // degree histogram
__device__ int    g_dcur[DEG_BINS];           // degree-bin cursors (exclusive scan)
__device__ int    g_perm[N_NODES];            // rows sorted by degree bucket
__device__ int2   g_edge[NNZ];                // compact {col, val bits}
__device__ __half g_b0[(size_t)N_NODES * EMB];
__device__ __half g_b1[(size_t)N_NODES * EMB];
__device__ __half g_b2[(size_t)N_NODES * EMB];
__device__ int    g_is64;

// ---------------- zero counts + fused dtype detection ----------------
// int64 indices (< 2^31): every odd 32-bit word is 0. int32: random node ids.
__global__ void k_zero_detect(const unsigned int* __restrict__ rowraw) {
    int i = blockIdx.x * blockDim.x + threadIdx.x;
    if (i < N_NODES) g_cursor[i] = 0;
    if (i < DEG_BINS) g_dbin[i] = 0;
    if (blockIdx.x == 0 && threadIdx.x == 0) {
        unsigned int acc = 0;
        #pragma unroll
        for (int j = 1; j < 128; j += 2) acc |= rowraw[j];
        g_is64 = (acc == 0u) ? 1 : 0;
    }
}

__device__ __forceinline__ int load_idx(const void* __restrict__ p, int e, int is64) {
    if (is64) return (int)((const long long*)p)[e];
    return ((const int*)p)[e];
}

// ---------------- CSR build (two-pass, compact) ----------------
__global__ void k_hist(const void* __restrict__ row) {
    int e = blockIdx.x * blockDim.x + threadIdx.x;
    int is64 = g_is64;
    if (e < NNZ) atomicAdd(&g_cursor[load_idx(row, e, is64)], 1);
}

__global__ void k_scan_chunks() {
    __shared__ int s[SCAN_CHUNK];
    int base = blockIdx.x * SCAN_CHUNK;
    int tid  = threadIdx.x;
    int i    = base + tid;
    int v    = (i < N_NODES) ? g_cursor[i] : 0;
    s[tid] = v;
    // fused degree histogram
    if (i < N_NODES) atomicAdd(&g_dbin[v < DEG_BINS - 1 ? v : DEG_BINS - 1], 1);
    __syncthreads();
    #pragma unroll
    for (int off = 1; off < SCAN_CHUNK; off <<= 1) {
        int t = (tid >= off) ? s[tid - off] : 0;
        __syncthreads();
        s[tid] += t;
        __syncthreads();
    }
    int incl = s[tid];
    if (i < N_NODES) g_rowptr[i] = incl - v;       // exclusive
    if (tid == SCAN_CHUNK - 1) g_bsum[blockIdx.x] = incl;
}

__global__ void k_scan_bsum() {
    __shared__ int s[256];
    int tid = threadIdx.x;
    int v = (tid < NUM_CHUNKS) ? g_bsum[tid] : 0;
    s[tid] = v;
    __syncthreads();
    #pragma unroll
    for (int off = 1; off < 256; off <<= 1) {
        int t = (tid >= off) ? s[tid - off] : 0;
        __syncthreads();
        s[tid] += t;
        __syncthreads();
    }
    if (tid < NUM_CHUNKS) g_bsum2[tid] = s[tid] - v;
    // fused exclusive scan of the 64 degree bins (serial, trivial)
    if (tid == 0) {
        int run = 0;
        #pragma unroll
        for (int b = 0; b < DEG_BINS; b++) { g_dcur[b] = run; run += g_dbin[b]; }
    }
}

__global__ void k_finalize_ptr() {
    int i = blockIdx.x * blockDim.x + threadIdx.x;
    if (i < N_NODES) {
        int cnt = g_cursor[i];                       // still the count
        int v = g_rowptr[i] + g_bsum2[i / SCAN_CHUNK];
        g_rowptr[i] = v;
        g_cursor[i] = v;                             // scatter cursor
        // degree-bucketed permutation
        int b = cnt < DEG_BINS - 1 ? cnt : DEG_BINS - 1;
        int p = atomicAdd(&g_dcur[b], 1);
        g_perm[p] = i;
        if (i == 0) g_rowptr[N_NODES] = NNZ;
    }
}

__global__ void k_scatter(const void* __restrict__ row,
                          const void* __restrict__ col,
                          const float* __restrict__ val) {
    int e = blockIdx.x * blockDim.x + threadIdx.x;
    int is64 = g_is64;
    if (e < NNZ) {
        int r = load_idx(row, e, is64);
        int p = atomicAdd(&g_cursor[r], 1);
        int2 ed;
        ed.x = load_idx(col, e, is64);
        ed.y = __float_as_int(val[e]);
        g_edge[p] = ed;
    }
}

// ---------------- ego init (fp32 -> fp16), vectorized 8 elems/thread ----------------
__global__ void k_init(const float4* __restrict__ user,
                       const float4* __restrict__ item,
                       uint4* __restrict__ b0) {
    const size_t TOT4 = (size_t)N_NODES * EMB / 4;        // float4 count
    const size_t U4   = (size_t)USER_NUM * EMB / 4;
    size_t i = ((size_t)blockIdx.x * blockDim.x + threadIdx.x) * 2;  // 2 float4 = 8 floats
    if (i >= TOT4) return;
    float4 f0 = (i     < U4) ? user[i]     : item[i - U4];
    float4 f1 = (i + 1 < U4) ? user[i + 1] : item[i + 1 - U4];
    uint4 o;
    __half2 h;
    h = __floats2half2_rn(f0.x, f0.y); o.x = *reinterpret_cast<unsigned int*>(&h);
    h = __floats2half2_rn(f0.z, f0.w); o.y = *reinterpret_cast<unsigned int*>(&h);
    h = __floats2half2_rn(f1.x, f1.y); o.z = *reinterpret_cast<unsigned int*>(&h);
    h = __floats2half2_rn(f1.z, f1.w); o.w = *reinterpret_cast<unsigned int*>(&h);
    b0[i / 2] = o;
}

// ---------------- SpMM: 8 lanes per row, LDG.128 gathers, degree-sorted rows ----------------
__device__ __forceinline__ void fma_h2(float& a0, float& a1, float v, unsigned int bits) {
    __half2 h = *reinterpret_cast<const __half2*>(&bits);
    float2 f = __half22float2(h);
    a0 = fmaf(v, f.x, a0);
    a1 = fmaf(v, f.y, a1);
}

__device__ __forceinline__ void spmm_slice(const uint4* __restrict__ x,
                                           int row, int sub, float* a) {
    int s = g_rowptr[row];
    int e = g_rowptr[row + 1];
    #pragma unroll 4
    for (int k = s; k < e; k++) {
        int2 ed = __ldg(&g_edge[k]);
        float v = __int_as_float(ed.y);
        uint4 q = __ldg(&x[(size_t)ed.x * ROWU4 + sub]);
        fma_h2(a[0], a[1], v, q.x);
        fma_h2(a[2], a[3], v, q.y);
        fma_h2(a[4], a[5], v, q.z);
        fma_h2(a[6], a[7], v, q.w);
    }
}

__device__ __forceinline__ unsigned int pack_h2(float lo, float hi) {
    __half2 h = __floats2half2_rn(lo, hi);
    return *reinterpret_cast<unsigned int*>(&h);
}

__global__ void __launch_bounds__(256)
k_spmm_mid(const uint4* __restrict__ x, uint4* __restrict__ y) {
    int t   = blockIdx.x * blockDim.x + threadIdx.x;
    int vr  = t >> 3;
    int sub = t & 7;
    if (vr >= N_NODES) return;
    int row = g_perm[vr];
    float a[8] = {0, 0, 0, 0, 0, 0, 0, 0};
    spmm_slice(x, row, sub, a);
    uint4 o;
    o.x = pack_h2(a[0], a[1]);
    o.y = pack_h2(a[2], a[3]);
    o.z = pack_h2(a[4], a[5]);
    o.w = pack_h2(a[6], a[7]);
    y[(size_t)row * ROWU4 + sub] = o;
}

// Layer 3: fuse the (e1 + e2 + e3)/3 reduction, write fp32 output directly.
__global__ void __launch_bounds__(256)
k_spmm_last(const uint4* __restrict__ x,      // = e2 (gather source)
            const uint4* __restrict__ e1,
            float* __restrict__ out) {
    int t   = blockIdx.x * blockDim.x + threadIdx.x;
    int vr  = t >> 3;
    int sub = t & 7;
    if (vr >= N_NODES) return;
    int row = g_perm[vr];
    float a[8] = {0, 0, 0, 0, 0, 0, 0, 0};
    spmm_slice(x, row, sub, a);

    uint4 q1 = e1[(size_t)row * ROWU4 + sub];
    uint4 q2 = x [(size_t)row * ROWU4 + sub];
    const unsigned int* p1 = &q1.x;
    const unsigned int* p2 = &q2.x;
    float r[8];
    #pragma unroll
    for (int j = 0; j < 4; j++) {
        float2 f1 = __half22float2(*reinterpret_cast<const __half2*>(&p1[j]));
        float2 f2 = __half22float2(*reinterpret_cast<const __half2*>(&p2[j]));
        r[2 * j + 0] = (f1.x + f2.x + a[2 * j + 0]) * (1.0f / 3.0f);
        r[2 * j + 1] = (f1.y + f2.y + a[2 * j + 1]) * (1.0f / 3.0f);
    }
    float4* op = reinterpret_cast<float4*>(out + (size_t)row * EMB + sub * 8);
    op[0] = make_float4(r[0], r[1], r[2], r[3]);
    op[1] = make_float4(r[4], r[5], r[6], r[7]);
}

extern "C" void kernel_launch(void* const* d_in, const int* in_sizes, int n_in,
                              void* d_out, int out_size) {
    const float* user = (const float*)d_in[0];
    const float* item = (const float*)d_in[1];
    const void*  arow = d_in[2];
    const void*  acol = d_in[3];
    const float* aval = (const float*)d_in[4];
    float* out = (float*)d_out;

    uint4 *b0, *b1, *b2;
    cudaGetSymbolAddress((void**)&b0, g_b0);
    cudaGetSymbolAddress((void**)&b1, g_b1);
    cudaGetSymbolAddress((void**)&b2, g_b2);

    const int T = 256;
    const int nodeBlocks = (N_NODES + T - 1) / T;
    const int edgeBlocks = (NNZ + T - 1) / T;
    const int init8      = (int)((size_t)N_NODES * EMB / 8);
    const int initBlocks = (init8 + T - 1) / T;
    const int spmmBlocks = (N_NODES * 8 + T - 1) / T;   // 8 lanes per row

    // ---- build compact CSR + degree-sorted row permutation ----
    k_zero_detect<<<nodeBlocks, T>>>((const unsigned int*)arow);
    k_hist<<<edgeBlocks, T>>>(arow);
    k_scan_chunks<<<NUM_CHUNKS, SCAN_CHUNK>>>();
    k_scan_bsum<<<1, 256>>>();
    k_finalize_ptr<<<nodeBlocks, T>>>();
    k_scatter<<<edgeBlocks, T>>>(arow, acol, aval);

    // ---- init ego (fp16, vectorized) ----
    k_init<<<initBlocks, T>>>((const float4*)user, (const float4*)item, b0);

    // ---- 3 propagation layers; layer 3 fuses the mean reduction ----
    k_spmm_mid <<<spmmBlocks, T>>>(b0, b1);        // e1 = A @ ego0
    k_spmm_mid <<<spmmBlocks, T>>>(b1, b2);        // e2 = A @ e1
    k_spmm_last<<<spmmBlocks, T>>>(b2, b1, out);   // out = (e1+e2+A@e2)/3
}

// round 8
// speedup vs baseline: 1.0846x; 1.0846x over previous
#include <cuda_runtime.h>
#include <cuda_fp16.h>
#include <cstdint>

#define USER_NUM 100000
#define ITEM_NUM 100000
#define N_NODES  (USER_NUM + ITEM_NUM)   // 200000
#define EMB      64
#define ROWU4    8                       // 8 uint4 (16B) per row = 128B
#define NNZ      4000000
#define SCAN_CHUNK 1024
#define NUM_CHUNKS ((N_NODES + SCAN_CHUNK - 1) / SCAN_CHUNK)   // 196

// ---------------- scratch (allocation-free: __device__ globals) ----------------
__device__ int    g_rowptr[N_NODES + 1];
__device__ int    g_cursor[N_NODES];          // histogram counts, then scatter cursors
__device__ int    g_bsum[NUM_CHUNKS];
__device__ int    g_bsum2[NUM_CHUNKS];
__device__ int2   g_edge[NNZ];                // compact {col, val bits}
__device__ __half g_b0[(size_t)N_NODES * EMB];
__device__ __half g_b1[(size_t)N_NODES * EMB];
__device__ __half g_b2[(size_t)N_NODES * EMB];
__device__ int    g_is64;

// ---------------- zero counts + fused dtype detection ----------------
// int64 indices (< 2^31): every odd 32-bit word is 0. int32: random node ids.
__global__ void k_zero_detect(const unsigned int* __restrict__ rowraw) {
    int i = blockIdx.x * blockDim.x + threadIdx.x;
    if (i < N_NODES) g_cursor[i] = 0;
    if (blockIdx.x == 0 && threadIdx.x == 0) {
        unsigned int acc = 0;
        #pragma unroll
        for (int j = 1; j < 128; j += 2) acc |= rowraw[j];
        g_is64 = (acc == 0u) ? 1 : 0;
    }
}

__device__ __forceinline__ int load_idx(const void* __restrict__ p, int e, int is64) {
    if (is64) return (int)((const long long*)p)[e];
    return ((const int*)p)[e];
}

// ---------------- CSR build (two-pass, compact) ----------------
__global__ void k_hist(const void* __restrict__ row) {
    int e = blockIdx.x * blockDim.x + threadIdx.x;
    int is64 = g_is64;
    if (e < NNZ) atomicAdd(&g_cursor[load_idx(row, e, is64)], 1);
}

__global__ void k_scan_chunks() {
    __shared__ int s[SCAN_CHUNK];
    int base = blockIdx.x * SCAN_CHUNK;
    int tid  = threadIdx.x;
    int i    = base + tid;
    int v    = (i < N_NODES) ? g_cursor[i] : 0;
    s[tid] = v;
    __syncthreads();
    #pragma unroll
    for (int off = 1; off < SCAN_CHUNK; off <<= 1) {
        int t = (tid >= off) ? s[tid - off] : 0;
        __syncthreads();
        s[tid] += t;
        __syncthreads();
    }
    int incl = s[tid];
    if (i < N_NODES) g_rowptr[i] = incl - v;       // exclusive
    if (tid == SCAN_CHUNK - 1) g_bsum[blockIdx.x] = incl;
}

__global__ void k_scan_bsum() {
    __shared__ int s[256];
    int tid = threadIdx.x;
    int v = (tid < NUM_CHUNKS) ? g_bsum[tid] : 0;
    s[tid] = v;
    __syncthreads();
    #pragma unroll
    for (int off = 1; off < 256; off <<= 1) {
        int t = (tid >= off) ? s[tid - off] : 0;
        __syncthreads();
        s[tid] += t;
        __syncthreads();
    }
    if (tid < NUM_CHUNKS) g_bsum2[tid] = s[tid] - v;
}

__global__ void k_finalize_ptr() {
    int i = blockIdx.x * blockDim.x + threadIdx.x;
    if (i < N_NODES) {
        int v = g_rowptr[i] + g_bsum2[i / SCAN_CHUNK];
        g_rowptr[i] = v;
        g_cursor[i] = v;
        if (i == 0) g_rowptr[N_NODES] = NNZ;
    }
}

__global__ void k_scatter(const void* __restrict__ row,
                          const void* __restrict__ col,
                          const float* __restrict__ val) {
    int e = blockIdx.x * blockDim.x + threadIdx.x;
    int is64 = g_is64;
    if (e < NNZ) {
        int r = load_idx(row, e, is64);
        int p = atomicAdd(&g_cursor[r], 1);
        int2 ed;
        ed.x = load_idx(col, e, is64);
        ed.y = __float_as_int(val[e]);
        g_edge[p] = ed;
    }
}

// ---------------- ego init (fp32 -> fp16), vectorized 8 elems/thread ----------------
__global__ void k_init(const float4* __restrict__ user,
                       const float4* __restrict__ item,
                       uint4* __restrict__ b0) {
    const size_t TOT4 = (size_t)N_NODES * EMB / 4;        // float4 count
    const size_t U4   = (size_t)USER_NUM * EMB / 4;
    size_t i = ((size_t)blockIdx.x * blockDim.x + threadIdx.x) * 2;  // 2 float4 = 8 floats
    if (i >= TOT4) return;
    float4 f0 = (i     < U4) ? user[i]     : item[i - U4];
    float4 f1 = (i + 1 < U4) ? user[i + 1] : item[i + 1 - U4];
    uint4 o;
    __half2 h;
    h = __floats2half2_rn(f0.x, f0.y); o.x = *reinterpret_cast<unsigned int*>(&h);
    h = __floats2half2_rn(f0.z, f0.w); o.y = *reinterpret_cast<unsigned int*>(&h);
    h = __floats2half2_rn(f1.x, f1.y); o.z = *reinterpret_cast<unsigned int*>(&h);
    h = __floats2half2_rn(f1.z, f1.w); o.w = *reinterpret_cast<unsigned int*>(&h);
    b0[i / 2] = o;
}

// ---------------- SpMM: 8 lanes per row, shuffle-distributed edges ----------------
__device__ __forceinline__ void fma_h2(float& a0, float& a1, float v, unsigned int bits) {
    __half2 h = *reinterpret_cast<const __half2*>(&bits);
    float2 f = __half22float2(h);
    a0 = fmaf(v, f.x, a0);
    a1 = fmaf(v, f.y, a1);
}

// 8-lane group: each lane loads one edge (coalesced 64B per group), then the
// group broadcasts each edge via group-local shuffles and gathers LDG.128.
// Accumulation order per row identical to a serial k-loop.
__device__ __forceinline__ void spmm_slice(const uint4* __restrict__ x,
                                           int row, int sub, unsigned gmask,
                                           float* a) {
    int s = g_rowptr[row];
    int e = g_rowptr[row + 1];
    for (int k = s; k < e; k += 8) {
        int idx = k + sub;
        int2 ed = (idx < e) ? __ldg(&g_edge[idx]) : make_int2(0, 0);
        int rem = e - k;                      // uniform within the 8-lane group
        #pragma unroll
        for (int j = 0; j < 8; j++) {
            if (j < rem) {                    // uniform guard per group
                int   c = __shfl_sync(gmask, ed.x, j, 8);
                float v = __int_as_float(__shfl_sync(gmask, ed.y, j, 8));
                uint4 q = __ldg(&x[(size_t)c * ROWU4 + sub]);
                fma_h2(a[0], a[1], v, q.x);
                fma_h2(a[2], a[3], v, q.y);
                fma_h2(a[4], a[5], v, q.z);
                fma_h2(a[6], a[7], v, q.w);
            }
        }
    }
}

__device__ __forceinline__ unsigned int pack_h2(float lo, float hi) {
    __half2 h = __floats2half2_rn(lo, hi);
    return *reinterpret_cast<unsigned int*>(&h);
}

__global__ void __launch_bounds__(256)
k_spmm_mid(const uint4* __restrict__ x, uint4* __restrict__ y) {
    int t   = blockIdx.x * blockDim.x + threadIdx.x;
    int row = t >> 3;
    int sub = t & 7;
    if (row >= N_NODES) return;
    unsigned gmask = 0xFFu << (threadIdx.x & 24);
    float a[8] = {0, 0, 0, 0, 0, 0, 0, 0};
    spmm_slice(x, row, sub, gmask, a);
    uint4 o;
    o.x = pack_h2(a[0], a[1]);
    o.y = pack_h2(a[2], a[3]);
    o.z = pack_h2(a[4], a[5]);
    o.w = pack_h2(a[6], a[7]);
    y[(size_t)row * ROWU4 + sub] = o;
}

// Layer 3: fuse the (e1 + e2 + e3)/3 reduction, write fp32 output directly.
__global__ void __launch_bounds__(256)
k_spmm_last(const uint4* __restrict__ x,      // = e2 (gather source)
            const uint4* __restrict__ e1,
            float* __restrict__ out) {
    int t   = blockIdx.x * blockDim.x + threadIdx.x;
    int row = t >> 3;
    int sub = t & 7;
    if (row >= N_NODES) return;
    unsigned gmask = 0xFFu << (threadIdx.x & 24);
    float a[8] = {0, 0, 0, 0, 0, 0, 0, 0};
    spmm_slice(x, row, sub, gmask, a);

    uint4 q1 = e1[(size_t)row * ROWU4 + sub];
    uint4 q2 = x [(size_t)row * ROWU4 + sub];
    const unsigned int* p1 = &q1.x;
    const unsigned int* p2 = &q2.x;
    float r[8];
    #pragma unroll
    for (int j = 0; j < 4; j++) {
        float2 f1 = __half22float2(*reinterpret_cast<const __half2*>(&p1[j]));
        float2 f2 = __half22float2(*reinterpret_cast<const __half2*>(&p2[j]));
        r[2 * j + 0] = (f1.x + f2.x + a[2 * j + 0]) * (1.0f / 3.0f);
        r[2 * j + 1] = (f1.y + f2.y + a[2 * j + 1]) * (1.0f / 3.0f);
    }
    float4* op = reinterpret_cast<float4*>(out + (size_t)row * EMB + sub * 8);
    op[0] = make_float4(r[0], r[1], r[2], r[3]);
    op[1] = make_float4(r[4], r[5], r[6], r[7]);
}

extern "C" void kernel_launch(void* const* d_in, const int* in_sizes, int n_in,
                              void* d_out, int out_size) {
    const float* user = (const float*)d_in[0];
    const float* item = (const float*)d_in[1];
    const void*  arow = d_in[2];
    const void*  acol = d_in[3];
    const float* aval = (const float*)d_in[4];
    float* out = (float*)d_out;

    uint4 *b0, *b1, *b2;
    cudaGetSymbolAddress((void**)&b0, g_b0);
    cudaGetSymbolAddress((void**)&b1, g_b1);
    cudaGetSymbolAddress((void**)&b2, g_b2);

    const int T = 256;
    const int nodeBlocks = (N_NODES + T - 1) / T;
    const int edgeBlocks = (NNZ + T - 1) / T;
    const int init8      = (int)((size_t)N_NODES * EMB / 8);
    const int initBlocks = (init8 + T - 1) / T;
    const int spmmBlocks = (N_NODES * 8 + T - 1) / T;   // 8 lanes per row

    // ---- build compact CSR (two-pass) ----
    k_zero_detect<<<nodeBlocks, T>>>((const unsigned int*)arow);
    k_hist<<<edgeBlocks, T>>>(arow);
    k_scan_chunks<<<NUM_CHUNKS, SCAN_CHUNK>>>();
    k_scan_bsum<<<1, 256>>>();
    k_finalize_ptr<<<nodeBlocks, T>>>();
    k_scatter<<<edgeBlocks, T>>>(arow, acol, aval);

    // ---- init ego (fp16, vectorized) ----
    k_init<<<initBlocks, T>>>((const float4*)user, (const float4*)item, b0);

    // ---- 3 propagation layers; layer 3 fuses the mean reduction ----
    k_spmm_mid <<<spmmBlocks, T>>>(b0, b1);        // e1 = A @ ego0
    k_spmm_mid <<<spmmBlocks, T>>>(b1, b2);        // e2 = A @ e1
    k_spmm_last<<<spmmBlocks, T>>>(b2, b1, out);   // out = (e1+e2+A@e2)/3
}

// round 9
// speedup vs baseline: 1.2078x; 1.1136x over previous
#include <cuda_runtime.h>
#include <cuda_fp16.h>
#include <cstdint>

#define USER_NUM 100000
#define ITEM_NUM 100000
#define N_NODES  (USER_NUM + ITEM_NUM)   // 200000
#define EMB      64
#define ROWU4    8                       // 8 uint4 (16B) per row = 128B
#define NNZ      4000000
#define SCAN_CHUNK 1024
#define NUM_CHUNKS ((N_NODES + SCAN_CHUNK - 1) / SCAN_CHUNK)   // 196

// ---------------- scratch (allocation-free: __device__ globals) ----------------
__device__ int    g_rowptr[N_NODES + 1];
__device__ int    g_cursor[N_NODES];          // histogram counts, then scatter cursors
__device__ int    g_bsum[NUM_CHUNKS];
__device__ int    g_bsum2[NUM_CHUNKS];
__device__ int2   g_edge[NNZ];                // compact {col, val bits}
__device__ __half g_b0[(size_t)N_NODES * EMB];
__device__ __half g_b1[(size_t)N_NODES * EMB];
__device__ __half g_b2[(size_t)N_NODES * EMB];
__device__ int    g_is64;

// ---------------- zero counts + fused dtype detection ----------------
// int64 indices (< 2^31): every odd 32-bit word is 0. int32: random node ids.
__global__ void k_zero_detect(const unsigned int* __restrict__ rowraw) {
    int i = blockIdx.x * blockDim.x + threadIdx.x;
    if (i < N_NODES) g_cursor[i] = 0;
    if (blockIdx.x == 0 && threadIdx.x == 0) {
        unsigned int acc = 0;
        #pragma unroll
        for (int j = 1; j < 128; j += 2) acc |= rowraw[j];
        g_is64 = (acc == 0u) ? 1 : 0;
    }
}

__device__ __forceinline__ int load_idx(const void* __restrict__ p, int e, int is64) {
    if (is64) return (int)((const long long*)p)[e];
    return ((const int*)p)[e];
}

// ---------------- CSR build (two-pass, compact) ----------------
__global__ void k_hist(const void* __restrict__ row) {
    int e = blockIdx.x * blockDim.x + threadIdx.x;
    int is64 = g_is64;
    if (e < NNZ) atomicAdd(&g_cursor[load_idx(row, e, is64)], 1);
}

__global__ void k_scan_chunks() {
    __shared__ int s[SCAN_CHUNK];
    int base = blockIdx.x * SCAN_CHUNK;
    int tid  = threadIdx.x;
    int i    = base + tid;
    int v    = (i < N_NODES) ? g_cursor[i] : 0;
    s[tid] = v;
    __syncthreads();
    #pragma unroll
    for (int off = 1; off < SCAN_CHUNK; off <<= 1) {
        int t = (tid >= off) ? s[tid - off] : 0;
        __syncthreads();
        s[tid] += t;
        __syncthreads();
    }
    int incl = s[tid];
    if (i < N_NODES) g_rowptr[i] = incl - v;       // exclusive
    if (tid == SCAN_CHUNK - 1) g_bsum[blockIdx.x] = incl;
}

__global__ void k_scan_bsum() {
    __shared__ int s[256];
    int tid = threadIdx.x;
    int v = (tid < NUM_CHUNKS) ? g_bsum[tid] : 0;
    s[tid] = v;
    __syncthreads();
    #pragma unroll
    for (int off = 1; off < 256; off <<= 1) {
        int t = (tid >= off) ? s[tid - off] : 0;
        __syncthreads();
        s[tid] += t;
        __syncthreads();
    }
    if (tid < NUM_CHUNKS) g_bsum2[tid] = s[tid] - v;
}

__global__ void k_finalize_ptr() {
    int i = blockIdx.x * blockDim.x + threadIdx.x;
    if (i < N_NODES) {
        int v = g_rowptr[i] + g_bsum2[i / SCAN_CHUNK];
        g_rowptr[i] = v;
        g_cursor[i] = v;
        if (i == 0) g_rowptr[N_NODES] = NNZ;
    }
}

__global__ void k_scatter(const void* __restrict__ row,
                          const void* __restrict__ col,
                          const float* __restrict__ val) {
    int e = blockIdx.x * blockDim.x + threadIdx.x;
    int is64 = g_is64;
    if (e < NNZ) {
        int r = load_idx(row, e, is64);
        int p = atomicAdd(&g_cursor[r], 1);
        int2 ed;
        ed.x = load_idx(col, e, is64);
        ed.y = __float_as_int(val[e]);
        g_edge[p] = ed;
    }
}

// ---------------- ego init (fp32 -> fp16), vectorized 8 elems/thread ----------------
__global__ void k_init(const float4* __restrict__ user,
                       const float4* __restrict__ item,
                       uint4* __restrict__ b0) {
    const size_t TOT4 = (size_t)N_NODES * EMB / 4;        // float4 count
    const size_t U4   = (size_t)USER_NUM * EMB / 4;
    size_t i = ((size_t)blockIdx.x * blockDim.x + threadIdx.x) * 2;  // 2 float4 = 8 floats
    if (i >= TOT4) return;
    float4 f0 = (i     < U4) ? user[i]     : item[i - U4];
    float4 f1 = (i + 1 < U4) ? user[i + 1] : item[i + 1 - U4];
    uint4 o;
    __half2 h;
    h = __floats2half2_rn(f0.x, f0.y); o.x = *reinterpret_cast<unsigned int*>(&h);
    h = __floats2half2_rn(f0.z, f0.w); o.y = *reinterpret_cast<unsigned int*>(&h);
    h = __floats2half2_rn(f1.x, f1.y); o.z = *reinterpret_cast<unsigned int*>(&h);
    h = __floats2half2_rn(f1.z, f1.w); o.w = *reinterpret_cast<unsigned int*>(&h);
    b0[i / 2] = o;
}

// ---------------- SpMM: 8 lanes per row, LDG.128 gathers (R6 structure) ----------------
__device__ __forceinline__ void fma_h2(float& a0, float& a1, float v, unsigned int bits) {
    __half2 h = *reinterpret_cast<const __half2*>(&bits);
    float2 f = __half22float2(h);
    a0 = fmaf(v, f.x, a0);
    a1 = fmaf(v, f.y, a1);
}

// Accumulate this (row, sub) slice: 8 floats (4 half2 = 16B of the 128B row).
__device__ __forceinline__ void spmm_slice(const uint4* __restrict__ x,
                                           int row, int sub, float* a) {
    int s = g_rowptr[row];
    int e = g_rowptr[row + 1];
    #pragma unroll 8
    for (int k = s; k < e; k++) {
        int2 ed = __ldg(&g_edge[k]);
        float v = __int_as_float(ed.y);
        uint4 q = __ldg(&x[(size_t)ed.x * ROWU4 + sub]);
        fma_h2(a[0], a[1], v, q.x);
        fma_h2(a[2], a[3], v, q.y);
        fma_h2(a[4], a[5], v, q.z);
        fma_h2(a[6], a[7], v, q.w);
    }
}

__device__ __forceinline__ unsigned int pack_h2(float lo, float hi) {
    __half2 h = __floats2half2_rn(lo, hi);
    return *reinterpret_cast<unsigned int*>(&h);
}

__global__ void __launch_bounds__(256)
k_spmm_mid(const uint4* __restrict__ x, uint4* __restrict__ y) {
    int t   = blockIdx.x * blockDim.x + threadIdx.x;
    int row = t >> 3;
    int sub = t & 7;
    if (row >= N_NODES) return;
    float a[8] = {0, 0, 0, 0, 0, 0, 0, 0};
    spmm_slice(x, row, sub, a);
    uint4 o;
    o.x = pack_h2(a[0], a[1]);
    o.y = pack_h2(a[2], a[3]);
    o.z = pack_h2(a[4], a[5]);
    o.w = pack_h2(a[6], a[7]);
    y[(size_t)row * ROWU4 + sub] = o;
}

// Layer 3: fuse the (e1 + e2 + e3)/3 reduction, write fp32 output directly.
__global__ void __launch_bounds__(256)
k_spmm_last(const uint4* __restrict__ x,      // = e2 (gather source)
            const uint4* __restrict__ e1,
            float* __restrict__ out) {
    int t   = blockIdx.x * blockDim.x + threadIdx.x;
    int row = t >> 3;
    int sub = t & 7;
    if (row >= N_NODES) return;
    float a[8] = {0, 0, 0, 0, 0, 0, 0, 0};
    spmm_slice(x, row, sub, a);

    uint4 q1 = e1[(size_t)row * ROWU4 + sub];
    uint4 q2 = x [(size_t)row * ROWU4 + sub];
    const unsigned int* p1 = &q1.x;
    const unsigned int* p2 = &q2.x;
    float r[8];
    #pragma unroll
    for (int j = 0; j < 4; j++) {
        float2 f1 = __half22float2(*reinterpret_cast<const __half2*>(&p1[j]));
        float2 f2 = __half22float2(*reinterpret_cast<const __half2*>(&p2[j]));
        r[2 * j + 0] = (f1.x + f2.x + a[2 * j + 0]) * (1.0f / 3.0f);
        r[2 * j + 1] = (f1.y + f2.y + a[2 * j + 1]) * (1.0f / 3.0f);
    }
    float4* op = reinterpret_cast<float4*>(out + (size_t)row * EMB + sub * 8);
    op[0] = make_float4(r[0], r[1], r[2], r[3]);
    op[1] = make_float4(r[4], r[5], r[6], r[7]);
}

extern "C" void kernel_launch(void* const* d_in, const int* in_sizes, int n_in,
                              void* d_out, int out_size) {
    const float* user = (const float*)d_in[0];
    const float* item = (const float*)d_in[1];
    const void*  arow = d_in[2];
    const void*  acol = d_in[3];
    const float* aval = (const float*)d_in[4];
    float* out = (float*)d_out;

    uint4 *b0, *b1, *b2;
    cudaGetSymbolAddress((void**)&b0, g_b0);
    cudaGetSymbolAddress((void**)&b1, g_b1);
    cudaGetSymbolAddress((void**)&b2, g_b2);

    const int T = 256;
    const int nodeBlocks = (N_NODES + T - 1) / T;
    const int edgeBlocks = (NNZ + T - 1) / T;
    const int init8      = (int)((size_t)N_NODES * EMB / 8);
    const int initBlocks = (init8 + T - 1) / T;
    const int spmmBlocks = (N_NODES * 8 + T - 1) / T;   // 8 lanes per row

    // ---- build compact CSR (two-pass) ----
    k_zero_detect<<<nodeBlocks, T>>>((const unsigned int*)arow);
    k_hist<<<edgeBlocks, T>>>(arow);
    k_scan_chunks<<<NUM_CHUNKS, SCAN_CHUNK>>>();
    k_scan_bsum<<<1, 256>>>();
    k_finalize_ptr<<<nodeBlocks, T>>>();
    k_scatter<<<edgeBlocks, T>>>(arow, acol, aval);

    // ---- init ego (fp16, vectorized) ----
    k_init<<<initBlocks, T>>>((const float4*)user, (const float4*)item, b0);

    // ---- 3 propagation layers; layer 3 fuses the mean reduction ----
    k_spmm_mid <<<spmmBlocks, T>>>(b0, b1);        // e1 = A @ ego0
    k_spmm_mid <<<spmmBlocks, T>>>(b1, b2);        // e2 = A @ e1
    k_spmm_last<<<spmmBlocks, T>>>(b2, b1, out);   // out = (e1+e2+A@e2)/3
}

// round 10
// speedup vs baseline: 1.2141x; 1.0052x over previous
#include <cuda_runtime.h>
#include <cuda_fp16.h>
#include <cstdint>

#define USER_NUM 100000
#define ITEM_NUM 100000
#define N_NODES  (USER_NUM + ITEM_NUM)   // 200000
#define EMB      64
#define ROWU4    8                       // 8 uint4 (16B) per row = 128B
#define NNZ      4000000
#define SCAN_CHUNK 1024
#define NUM_CHUNKS ((N_NODES + SCAN_CHUNK - 1) / SCAN_CHUNK)   // 196

// ---------------- scratch (allocation-free: __device__ globals) ----------------
__device__ int    g_rowptr[N_NODES + 1];
__device__ int    g_cursor[N_NODES];          // histogram counts, then scatter cursors
__device__ int    g_bsum[NUM_CHUNKS];
__device__ int    g_bsum2[NUM_CHUNKS];
__device__ int2   g_edge[NNZ];                // compact {col, val bits}
__device__ __half g_b0[(size_t)N_NODES * EMB];
__device__ __half g_b1[(size_t)N_NODES * EMB];
__device__ __half g_b2[(size_t)N_NODES * EMB];
__device__ int    g_is64;

// ---------------- zero counts + fused dtype detection ----------------
// int64 indices (< 2^31): every odd 32-bit word is 0. int32: random node ids.
__global__ void k_zero_detect(const unsigned int* __restrict__ rowraw) {
    int i = blockIdx.x * blockDim.x + threadIdx.x;
    if (i < N_NODES) g_cursor[i] = 0;
    if (blockIdx.x == 0 && threadIdx.x == 0) {
        unsigned int acc = 0;
        #pragma unroll
        for (int j = 1; j < 128; j += 2) acc |= rowraw[j];
        g_is64 = (acc == 0u) ? 1 : 0;
    }
}

// Load two consecutive indices (e, e+1) with streaming hint.
__device__ __forceinline__ int2 load_idx2(const void* __restrict__ p, int e, int is64) {
    if (is64) {
        longlong2 q = __ldcs((const longlong2*)p + (e >> 1));   // e is even
        return make_int2((int)q.x, (int)q.y);
    }
    return __ldcs((const int2*)p + (e >> 1));
}

// ---------------- CSR build (two-pass, compact, 2 edges/thread) ----------------
__global__ void k_hist(const void* __restrict__ row) {
    int e = (blockIdx.x * blockDim.x + threadIdx.x) * 2;
    int is64 = g_is64;
    if (e < NNZ) {
        int2 r = load_idx2(row, e, is64);
        atomicAdd(&g_cursor[r.x], 1);
        atomicAdd(&g_cursor[r.y], 1);
    }
}

__global__ void k_scan_chunks() {
    __shared__ int s[SCAN_CHUNK];
    int base = blockIdx.x * SCAN_CHUNK;
    int tid  = threadIdx.x;
    int i    = base + tid;
    int v    = (i < N_NODES) ? g_cursor[i] : 0;
    s[tid] = v;
    __syncthreads();
    #pragma unroll
    for (int off = 1; off < SCAN_CHUNK; off <<= 1) {
        int t = (tid >= off) ? s[tid - off] : 0;
        __syncthreads();
        s[tid] += t;
        __syncthreads();
    }
    int incl = s[tid];
    if (i < N_NODES) g_rowptr[i] = incl - v;       // exclusive
    if (tid == SCAN_CHUNK - 1) g_bsum[blockIdx.x] = incl;
}

__global__ void k_scan_bsum() {
    __shared__ int s[256];
    int tid = threadIdx.x;
    int v = (tid < NUM_CHUNKS) ? g_bsum[tid] : 0;
    s[tid] = v;
    __syncthreads();
    #pragma unroll
    for (int off = 1; off < 256; off <<= 1) {
        int t = (tid >= off) ? s[tid - off] : 0;
        __syncthreads();
        s[tid] += t;
        __syncthreads();
    }
    if (tid < NUM_CHUNKS) g_bsum2[tid] = s[tid] - v;
}

__global__ void k_finalize_ptr() {
    int i = blockIdx.x * blockDim.x + threadIdx.x;
    if (i < N_NODES) {
        int v = g_rowptr[i] + g_bsum2[i / SCAN_CHUNK];
        g_rowptr[i] = v;
        g_cursor[i] = v;
        if (i == 0) g_rowptr[N_NODES] = NNZ;
    }
}

__global__ void k_scatter(const void* __restrict__ row,
                          const void* __restrict__ col,
                          const float* __restrict__ val) {
    int e = (blockIdx.x * blockDim.x + threadIdx.x) * 2;
    int is64 = g_is64;
    if (e < NNZ) {
        int2   r = load_idx2(row, e, is64);
        int2   c = load_idx2(col, e, is64);
        float2 v = __ldcs((const float2*)val + (e >> 1));
        int p0 = atomicAdd(&g_cursor[r.x], 1);
        g_edge[p0] = make_int2(c.x, __float_as_int(v.x));
        int p1 = atomicAdd(&g_cursor[r.y], 1);
        g_edge[p1] = make_int2(c.y, __float_as_int(v.y));
    }
}

// ---------------- ego init (fp32 -> fp16), vectorized 8 elems/thread ----------------
__global__ void k_init(const float4* __restrict__ user,
                       const float4* __restrict__ item,
                       uint4* __restrict__ b0) {
    const size_t TOT4 = (size_t)N_NODES * EMB / 4;        // float4 count
    const size_t U4   = (size_t)USER_NUM * EMB / 4;
    size_t i = ((size_t)blockIdx.x * blockDim.x + threadIdx.x) * 2;  // 2 float4 = 8 floats
    if (i >= TOT4) return;
    float4 f0 = (i     < U4) ? __ldcs(user + i)     : __ldcs(item + (i - U4));
    float4 f1 = (i + 1 < U4) ? __ldcs(user + i + 1) : __ldcs(item + (i + 1 - U4));
    uint4 o;
    __half2 h;
    h = __floats2half2_rn(f0.x, f0.y); o.x = *reinterpret_cast<unsigned int*>(&h);
    h = __floats2half2_rn(f0.z, f0.w); o.y = *reinterpret_cast<unsigned int*>(&h);
    h = __floats2half2_rn(f1.x, f1.y); o.z = *reinterpret_cast<unsigned int*>(&h);
    h = __floats2half2_rn(f1.z, f1.w); o.w = *reinterpret_cast<unsigned int*>(&h);
    b0[i / 2] = o;
}

// ---------------- SpMM: 8 lanes per row, LDG.128 gathers (R6/R9 structure) ----------------
__device__ __forceinline__ void fma_h2(float& a0, float& a1, float v, unsigned int bits) {
    __half2 h = *reinterpret_cast<const __half2*>(&bits);
    float2 f = __half22float2(h);
    a0 = fmaf(v, f.x, a0);
    a1 = fmaf(v, f.y, a1);
}

// Accumulate this (row, sub) slice: 8 floats (4 half2 = 16B of the 128B row).
__device__ __forceinline__ void spmm_slice(const uint4* __restrict__ x,
                                           int row, int sub, float* a) {
    int s = g_rowptr[row];
    int e = g_rowptr[row + 1];
    #pragma unroll 8
    for (int k = s; k < e; k++) {
        int2 ed = __ldg(&g_edge[k]);
        float v = __int_as_float(ed.y);
        uint4 q = __ldg(&x[(size_t)ed.x * ROWU4 + sub]);
        fma_h2(a[0], a[1], v, q.x);
        fma_h2(a[2], a[3], v, q.y);
        fma_h2(a[4], a[5], v, q.z);
        fma_h2(a[6], a[7], v, q.w);
    }
}

__device__ __forceinline__ unsigned int pack_h2(float lo, float hi) {
    __half2 h = __floats2half2_rn(lo, hi);
    return *reinterpret_cast<unsigned int*>(&h);
}

__global__ void __launch_bounds__(256)
k_spmm_mid(const uint4* __restrict__ x, uint4* __restrict__ y) {
    int t   = blockIdx.x * blockDim.x + threadIdx.x;
    int row = t >> 3;
    int sub = t & 7;
    if (row >= N_NODES) return;
    float a[8] = {0, 0, 0, 0, 0, 0, 0, 0};
    spmm_slice(x, row, sub, a);
    uint4 o;
    o.x = pack_h2(a[0], a[1]);
    o.y = pack_h2(a[2], a[3]);
    o.z = pack_h2(a[4], a[5]);
    o.w = pack_h2(a[6], a[7]);
    y[(size_t)row * ROWU4 + sub] = o;
}

// Layer 3: fuse the (e1 + e2 + e3)/3 reduction, write fp32 output directly.
__global__ void __launch_bounds__(256)
k_spmm_last(const uint4* __restrict__ x,      // = e2 (gather source)
            const uint4* __restrict__ e1,
            float* __restrict__ out) {
    int t   = blockIdx.x * blockDim.x + threadIdx.x;
    int row = t >> 3;
    int sub = t & 7;
    if (row >= N_NODES) return;
    float a[8] = {0, 0, 0, 0, 0, 0, 0, 0};
    spmm_slice(x, row, sub, a);

    uint4 q1 = e1[(size_t)row * ROWU4 + sub];
    uint4 q2 = x [(size_t)row * ROWU4 + sub];
    const unsigned int* p1 = &q1.x;
    const unsigned int* p2 = &q2.x;
    float r[8];
    #pragma unroll
    for (int j = 0; j < 4; j++) {
        float2 f1 = __half22float2(*reinterpret_cast<const __half2*>(&p1[j]));
        float2 f2 = __half22float2(*reinterpret_cast<const __half2*>(&p2[j]));
        r[2 * j + 0] = (f1.x + f2.x + a[2 * j + 0]) * (1.0f / 3.0f);
        r[2 * j + 1] = (f1.y + f2.y + a[2 * j + 1]) * (1.0f / 3.0f);
    }
    float4* op = reinterpret_cast<float4*>(out + (size_t)row * EMB + sub * 8);
    op[0] = make_float4(r[0], r[1], r[2], r[3]);
    op[1] = make_float4(r[4], r[5], r[6], r[7]);
}

extern "C" void kernel_launch(void* const* d_in, const int* in_sizes, int n_in,
                              void* d_out, int out_size) {
    const float* user = (const float*)d_in[0];
    const float* item = (const float*)d_in[1];
    const void*  arow = d_in[2];
    const void*  acol = d_in[3];
    const float* aval = (const float*)d_in[4];
    float* out = (float*)d_out;

    uint4 *b0, *b1, *b2;
    cudaGetSymbolAddress((void**)&b0, g_b0);
    cudaGetSymbolAddress((void**)&b1, g_b1);
    cudaGetSymbolAddress((void**)&b2, g_b2);

    const int T = 256;
    const int nodeBlocks  = (N_NODES + T - 1) / T;
    const int edgeBlocks2 = (NNZ / 2 + T - 1) / T;     // 2 edges per thread
    const int init8       = (int)((size_t)N_NODES * EMB / 8);
    const int initBlocks  = (init8 + T - 1) / T;
    const int spmmBlocks  = (N_NODES * 8 + T - 1) / T; // 8 lanes per row

    // ---- build compact CSR (two-pass, vectorized) ----
    k_zero_detect<<<nodeBlocks, T>>>((const unsigned int*)arow);
    k_hist<<<edgeBlocks2, T>>>(arow);
    k_scan_chunks<<<NUM_CHUNKS, SCAN_CHUNK>>>();
    k_scan_bsum<<<1, 256>>>();
    k_finalize_ptr<<<nodeBlocks, T>>>();
    k_scatter<<<edgeBlocks2, T>>>(arow, acol, aval);

    // ---- init ego (fp16, vectorized) ----
    k_init<<<initBlocks, T>>>((const float4*)user, (const float4*)item, b0);

    // ---- 3 propagation layers; layer 3 fuses the mean reduction ----
    k_spmm_mid <<<spmmBlocks, T>>>(b0, b1);        // e1 = A @ ego0
    k_spmm_mid <<<spmmBlocks, T>>>(b1, b2);        // e2 = A @ e1
    k_spmm_last<<<spmmBlocks, T>>>(b2, b1, out);   // out = (e1+e2+A@e2)/3
}

// round 11
// speedup vs baseline: 1.2151x; 1.0009x over previous
#include <cuda_runtime.h>
#include <cuda_fp16.h>
#include <cstdint>

#define USER_NUM 100000
#define ITEM_NUM 100000
#define N_NODES  (USER_NUM + ITEM_NUM)   // 200000
#define EMB      64
#define ROWU4    8                       // 8 uint4 (16B) per row = 128B
#define NNZ      4000000
#define SCAN_CHUNK 1024
#define NUM_CHUNKS ((N_NODES + SCAN_CHUNK - 1) / SCAN_CHUNK)   // 196

// ---------------- scratch (allocation-free: __device__ globals) ----------------
__device__ int    g_rowptr[N_NODES + 1];
__device__ int    g_cursor[N_NODES];          // histogram counts, then scatter cursors
__device__ int    g_bsum[NUM_CHUNKS];
__device__ int    g_bsum2[NUM_CHUNKS];
__device__ int2   g_edge[NNZ];                // compact {col, val bits}
__device__ __half g_b0[(size_t)N_NODES * EMB];
__device__ __half g_b1[(size_t)N_NODES * EMB];
__device__ __half g_b2[(size_t)N_NODES * EMB];
__device__ int    g_is64;

// ---------------- zero counts + fused dtype detection ----------------
// int64 indices (< 2^31): every odd 32-bit word is 0. int32: random node ids.
__global__ void k_zero_detect(const unsigned int* __restrict__ rowraw) {
    int i = blockIdx.x * blockDim.x + threadIdx.x;
    if (i < N_NODES) g_cursor[i] = 0;
    if (blockIdx.x == 0 && threadIdx.x == 0) {
        unsigned int acc = 0;
        #pragma unroll
        for (int j = 1; j < 128; j += 2) acc |= rowraw[j];
        g_is64 = (acc == 0u) ? 1 : 0;
    }
}

// Load two consecutive indices (e, e+1) with streaming hint.
__device__ __forceinline__ int2 load_idx2(const void* __restrict__ p, int e, int is64) {
    if (is64) {
        longlong2 q = __ldcs((const longlong2*)p + (e >> 1));   // e is even
        return make_int2((int)q.x, (int)q.y);
    }
    return __ldcs((const int2*)p + (e >> 1));
}

// ---------------- CSR build (two-pass, compact, 2 edges/thread) ----------------
__global__ void k_hist(const void* __restrict__ row) {
    int e = (blockIdx.x * blockDim.x + threadIdx.x) * 2;
    int is64 = g_is64;
    if (e < NNZ) {
        int2 r = load_idx2(row, e, is64);
        atomicAdd(&g_cursor[r.x], 1);
        atomicAdd(&g_cursor[r.y], 1);
    }
}

__global__ void k_scan_chunks() {
    __shared__ int s[SCAN_CHUNK];
    int base = blockIdx.x * SCAN_CHUNK;
    int tid  = threadIdx.x;
    int i    = base + tid;
    int v    = (i < N_NODES) ? g_cursor[i] : 0;
    s[tid] = v;
    __syncthreads();
    #pragma unroll
    for (int off = 1; off < SCAN_CHUNK; off <<= 1) {
        int t = (tid >= off) ? s[tid - off] : 0;
        __syncthreads();
        s[tid] += t;
        __syncthreads();
    }
    int incl = s[tid];
    if (i < N_NODES) g_rowptr[i] = incl - v;       // exclusive
    if (tid == SCAN_CHUNK - 1) g_bsum[blockIdx.x] = incl;
}

__global__ void k_scan_bsum() {
    __shared__ int s[256];
    int tid = threadIdx.x;
    int v = (tid < NUM_CHUNKS) ? g_bsum[tid] : 0;
    s[tid] = v;
    __syncthreads();
    #pragma unroll
    for (int off = 1; off < 256; off <<= 1) {
        int t = (tid >= off) ? s[tid - off] : 0;
        __syncthreads();
        s[tid] += t;
        __syncthreads();
    }
    if (tid < NUM_CHUNKS) g_bsum2[tid] = s[tid] - v;
}

__global__ void k_finalize_ptr() {
    int i = blockIdx.x * blockDim.x + threadIdx.x;
    if (i < N_NODES) {
        int v = g_rowptr[i] + g_bsum2[i / SCAN_CHUNK];
        g_rowptr[i] = v;
        g_cursor[i] = v;
        if (i == 0) g_rowptr[N_NODES] = NNZ;
    }
}

__global__ void k_scatter(const void* __restrict__ row,
                          const void* __restrict__ col,
                          const float* __restrict__ val) {
    int e = (blockIdx.x * blockDim.x + threadIdx.x) * 2;
    int is64 = g_is64;
    if (e < NNZ) {
        int2   r = load_idx2(row, e, is64);
        int2   c = load_idx2(col, e, is64);
        float2 v = __ldcs((const float2*)val + (e >> 1));
        int p0 = atomicAdd(&g_cursor[r.x], 1);
        g_edge[p0] = make_int2(c.x, __float_as_int(v.x));
        int p1 = atomicAdd(&g_cursor[r.y], 1);
        g_edge[p1] = make_int2(c.y, __float_as_int(v.y));
    }
}

// ---------------- ego init (fp32 -> fp16), vectorized 8 elems/thread ----------------
__global__ void k_init(const float4* __restrict__ user,
                       const float4* __restrict__ item,
                       uint4* __restrict__ b0) {
    const size_t TOT4 = (size_t)N_NODES * EMB / 4;        // float4 count
    const size_t U4   = (size_t)USER_NUM * EMB / 4;
    size_t i = ((size_t)blockIdx.x * blockDim.x + threadIdx.x) * 2;  // 2 float4 = 8 floats
    if (i >= TOT4) return;
    float4 f0 = (i     < U4) ? __ldcs(user + i)     : __ldcs(item + (i - U4));
    float4 f1 = (i + 1 < U4) ? __ldcs(user + i + 1) : __ldcs(item + (i + 1 - U4));
    uint4 o;
    __half2 h;
    h = __floats2half2_rn(f0.x, f0.y); o.x = *reinterpret_cast<unsigned int*>(&h);
    h = __floats2half2_rn(f0.z, f0.w); o.y = *reinterpret_cast<unsigned int*>(&h);
    h = __floats2half2_rn(f1.x, f1.y); o.z = *reinterpret_cast<unsigned int*>(&h);
    h = __floats2half2_rn(f1.z, f1.w); o.w = *reinterpret_cast<unsigned int*>(&h);
    b0[i / 2] = o;
}

// ---------------- SpMM: 8 lanes per row, LDG.128 gathers (R6/R9 structure) ----------------
__device__ __forceinline__ void fma_h2(float& a0, float& a1, float v, unsigned int bits) {
    __half2 h = *reinterpret_cast<const __half2*>(&bits);
    float2 f = __half22float2(h);
    a0 = fmaf(v, f.x, a0);
    a1 = fmaf(v, f.y, a1);
}

// Accumulate this (row, sub) slice: 8 floats (4 half2 = 16B of the 128B row).
__device__ __forceinline__ void spmm_slice(const uint4* __restrict__ x,
                                           int row, int sub, float* a) {
    int s = g_rowptr[row];
    int e = g_rowptr[row + 1];
    #pragma unroll 8
    for (int k = s; k < e; k++) {
        int2 ed = __ldg(&g_edge[k]);
        float v = __int_as_float(ed.y);
        uint4 q = __ldg(&x[(size_t)ed.x * ROWU4 + sub]);
        fma_h2(a[0], a[1], v, q.x);
        fma_h2(a[2], a[3], v, q.y);
        fma_h2(a[4], a[5], v, q.z);
        fma_h2(a[6], a[7], v, q.w);
    }
}

__device__ __forceinline__ unsigned int pack_h2(float lo, float hi) {
    __half2 h = __floats2half2_rn(lo, hi);
    return *reinterpret_cast<unsigned int*>(&h);
}

__global__ void __launch_bounds__(256, 8)     // force <=32 regs -> 64 warps/SM
k_spmm_mid(const uint4* __restrict__ x, uint4* __restrict__ y) {
    int t   = blockIdx.x * blockDim.x + threadIdx.x;
    int row = t >> 3;
    int sub = t & 7;
    if (row >= N_NODES) return;
    float a[8] = {0, 0, 0, 0, 0, 0, 0, 0};
    spmm_slice(x, row, sub, a);
    uint4 o;
    o.x = pack_h2(a[0], a[1]);
    o.y = pack_h2(a[2], a[3]);
    o.z = pack_h2(a[4], a[5]);
    o.w = pack_h2(a[6], a[7]);
    y[(size_t)row * ROWU4 + sub] = o;
}

// Layer 3: fuse the (e1 + e2 + e3)/3 reduction, write fp32 output directly.
__global__ void __launch_bounds__(256, 8)     // force <=32 regs -> 64 warps/SM
k_spmm_last(const uint4* __restrict__ x,      // = e2 (gather source)
            const uint4* __restrict__ e1,
            float* __restrict__ out) {
    int t   = blockIdx.x * blockDim.x + threadIdx.x;
    int row = t >> 3;
    int sub = t & 7;
    if (row >= N_NODES) return;
    float a[8] = {0, 0, 0, 0, 0, 0, 0, 0};
    spmm_slice(x, row, sub, a);

    uint4 q1 = e1[(size_t)row * ROWU4 + sub];
    uint4 q2 = x [(size_t)row * ROWU4 + sub];
    const unsigned int* p1 = &q1.x;
    const unsigned int* p2 = &q2.x;
    float r[8];
    #pragma unroll
    for (int j = 0; j < 4; j++) {
        float2 f1 = __half22float2(*reinterpret_cast<const __half2*>(&p1[j]));
        float2 f2 = __half22float2(*reinterpret_cast<const __half2*>(&p2[j]));
        r[2 * j + 0] = (f1.x + f2.x + a[2 * j + 0]) * (1.0f / 3.0f);
        r[2 * j + 1] = (f1.y + f2.y + a[2 * j + 1]) * (1.0f / 3.0f);
    }
    float4* op = reinterpret_cast<float4*>(out + (size_t)row * EMB + sub * 8);
    op[0] = make_float4(r[0], r[1], r[2], r[3]);
    op[1] = make_float4(r[4], r[5], r[6], r[7]);
}

extern "C" void kernel_launch(void* const* d_in, const int* in_sizes, int n_in,
                              void* d_out, int out_size) {
    const float* user = (const float*)d_in[0];
    const float* item = (const float*)d_in[1];
    const void*  arow = d_in[2];
    const void*  acol = d_in[3];
    const float* aval = (const float*)d_in[4];
    float* out = (float*)d_out;

    uint4 *b0, *b1, *b2;
    cudaGetSymbolAddress((void**)&b0, g_b0);
    cudaGetSymbolAddress((void**)&b1, g_b1);
    cudaGetSymbolAddress((void**)&b2, g_b2);

    const int T = 256;
    const int nodeBlocks  = (N_NODES + T - 1) / T;
    const int edgeBlocks2 = (NNZ / 2 + T - 1) / T;     // 2 edges per thread
    const int init8       = (int)((size_t)N_NODES * EMB / 8);
    const int initBlocks  = (init8 + T - 1) / T;
    const int spmmBlocks  = (N_NODES * 8 + T - 1) / T; // 8 lanes per row

    // ---- build compact CSR (two-pass, vectorized) ----
    k_zero_detect<<<nodeBlocks, T>>>((const unsigned int*)arow);
    k_hist<<<edgeBlocks2, T>>>(arow);
    k_scan_chunks<<<NUM_CHUNKS, SCAN_CHUNK>>>();
    k_scan_bsum<<<1, 256>>>();
    k_finalize_ptr<<<nodeBlocks, T>>>();
    k_scatter<<<edgeBlocks2, T>>>(arow, acol, aval);

    // ---- init ego (fp16, vectorized) ----
    k_init<<<initBlocks, T>>>((const float4*)user, (const float4*)item, b0);

    // ---- 3 propagation layers; layer 3 fuses the mean reduction ----
    k_spmm_mid <<<spmmBlocks, T>>>(b0, b1);        // e1 = A @ ego0
    k_spmm_mid <<<spmmBlocks, T>>>(b1, b2);        // e2 = A @ e1
    k_spmm_last<<<spmmBlocks, T>>>(b2, b1, out);   // out = (e1+e2+A@e2)/3
}